// round 6
// baseline (speedup 1.0000x reference)
#include <cuda_runtime.h>
#include <cstdint>

// CategorySpecificLinear via mma.sync.m16n8k8 TF32 (base sm_103; tcgen05 is
// rejected by this bench's ptxas target).
//
// Round 6: CTA tile 128(M) x 128(N), BK=16, 4 warps (2Mx2N), warp tile 64x64,
// __launch_bounds__(128, 2) -> 2 CTAs/SM so barrier/staging of one CTA
// overlaps MMA of the other. Padded SMEM layouts (A rows 20 f32, B rows 136
// f32), double-buffered stages, fp32->tf32 via cvt.rna at STS.

#define A_ROWB   80                        // 20 f32 per A row
#define STAGE_A  (128 * A_ROWB)            // 10240
#define B_ROWB   544                       // 136 f32 per B row
#define STAGE_B  (16 * B_ROWB)             // 8704
#define B_OFF    (2 * STAGE_A)             // 20480
#define SMEM_DYN (2 * STAGE_A + 2 * STAGE_B)   // 37888

static __device__ __forceinline__ uint32_t f2tf(float f){
    uint32_t r; asm("cvt.rna.tf32.f32 %0, %1;" : "=r"(r) : "f"(f)); return r;
}

static __device__ __forceinline__ void mma_tf32(float d[4],
                                                uint32_t a0, uint32_t a1,
                                                uint32_t a2, uint32_t a3,
                                                uint32_t b0, uint32_t b1){
    asm volatile(
        "mma.sync.aligned.m16n8k8.row.col.f32.tf32.tf32.f32 "
        "{%0,%1,%2,%3}, {%4,%5,%6,%7}, {%8,%9}, {%0,%1,%2,%3};"
        : "+f"(d[0]), "+f"(d[1]), "+f"(d[2]), "+f"(d[3])
        : "r"(a0), "r"(a1), "r"(a2), "r"(a3), "r"(b0), "r"(b1));
}

__global__ __launch_bounds__(128, 2)
void cslin_mma4_kernel(const float* __restrict__ x,
                       const int*   __restrict__ cat_ids,
                       const float* __restrict__ W,
                       const float* __restrict__ bias,
                       float*       __restrict__ y)
{
    constexpr int IDIM = 1024, ODIM = 1024, TDIM = 512;
    extern __shared__ char dsm[];

    const int tid  = threadIdx.x;        // 0..127
    const int wid  = tid >> 5;           // 0..3
    const int lane = tid & 31;
    const int la3  = lane & 3;
    const int lg   = lane >> 2;

    const int n0 = blockIdx.x * 128;
    const int m0 = blockIdx.y * 128;
    const int bb = blockIdx.z;
    const int cat = __ldg(cat_ids + bb);

    const float* xb = x + (size_t)bb  * TDIM * IDIM;
    const float* Wc = W + (size_t)cat * IDIM * ODIM;
    const float* bc = bias + (size_t)cat * ODIM;
    float*       yb = y + (size_t)bb  * TDIM * ODIM;

    // ---- loader geometry ----
    // A chunk 128m x 16k: one row per thread, 4 float4 at k = 0,4,8,12
    const float* aG = xb + (size_t)(m0 + tid) * IDIM;
    const uint32_t aS = (uint32_t)(tid * A_ROWB);            // + i*16 bytes
    // B chunk 16k x 128n: row = tid>>3, cols (tid&7)*4 + 32i
    const float* bG = Wc + (size_t)(tid >> 3) * ODIM + n0 + ((tid & 7) << 2);
    const uint32_t bS = (uint32_t)((tid >> 3) * B_ROWB + ((tid & 7) << 4)); // + i*128B

    // ---- warp tile 64x64 ----
    const int wm = (wid & 1) * 64;
    const int wn = (wid >> 1) * 64;

    uint32_t rA[4];
    #pragma unroll
    for (int i = 0; i < 4; i++) rA[i] = (uint32_t)((wm + i * 16 + lg) * A_ROWB);
    uint32_t bN[8];
    #pragma unroll
    for (int j = 0; j < 8; j++) bN[j] = (uint32_t)((wn + j * 8 + lg) * 4);
    const uint32_t aKoff = (uint32_t)(la3 * 4);
    const uint32_t bKrow = (uint32_t)(la3 * B_ROWB);

    float acc[4][8][4];
    #pragma unroll
    for (int i = 0; i < 4; i++)
        #pragma unroll
        for (int j = 0; j < 8; j++)
            #pragma unroll
            for (int q = 0; q < 4; q++) acc[i][j][q] = 0.f;

    float4 av[4], bv[4];

#define STAGE_STORE(STA, STB)                                                  \
    do {                                                                       \
        _Pragma("unroll")                                                      \
        for (int i = 0; i < 4; i++)                                            \
            *(uint4*)((STA) + aS + (uint32_t)(i * 16)) =                       \
                make_uint4(f2tf(av[i].x), f2tf(av[i].y),                       \
                           f2tf(av[i].z), f2tf(av[i].w));                      \
        _Pragma("unroll")                                                      \
        for (int i = 0; i < 4; i++)                                            \
            *(uint4*)((STB) + bS + (uint32_t)(i * 128)) =                      \
                make_uint4(f2tf(bv[i].x), f2tf(bv[i].y),                       \
                           f2tf(bv[i].z), f2tf(bv[i].w));                      \
    } while (0)

    // ---- prologue: chunk 0 ----
    #pragma unroll
    for (int i = 0; i < 4; i++) av[i] = *(const float4*)(aG + 4 * i);
    #pragma unroll
    for (int i = 0; i < 4; i++) bv[i] = *(const float4*)(bG + 32 * i);
    STAGE_STORE(dsm, dsm + B_OFF);
    __syncthreads();

    // ---- main loop: 64 K-chunks of 16 ----
    for (int c = 0; c < 64; c++){
        const int s = c & 1;
        const char* stA = dsm + s * STAGE_A;
        const char* stB = dsm + B_OFF + s * STAGE_B;

        if (c < 63){
            const int kc = (c + 1) * 16;
            #pragma unroll
            for (int i = 0; i < 4; i++)
                av[i] = *(const float4*)(aG + kc + 4 * i);
            #pragma unroll
            for (int i = 0; i < 4; i++)
                bv[i] = *(const float4*)(bG + (size_t)kc * ODIM + 32 * i);
        }

        // ---- 2 k-steps of 8 ----
        #pragma unroll
        for (int ks = 0; ks < 2; ks++){
            uint32_t b0[8], b1[8];
            const char* pb = stB + bKrow + ks * (8 * B_ROWB);
            #pragma unroll
            for (int j = 0; j < 8; j++){
                b0[j] = *(const uint32_t*)(pb + bN[j]);
                b1[j] = *(const uint32_t*)(pb + bN[j] + 4 * B_ROWB);
            }
            #pragma unroll
            for (int i = 0; i < 4; i++){
                const char* pa = stA + rA[i] + aKoff + ks * 32;
                const uint32_t a0 = *(const uint32_t*)(pa);
                const uint32_t a1 = *(const uint32_t*)(pa + 8 * A_ROWB);
                const uint32_t a2 = *(const uint32_t*)(pa + 16);
                const uint32_t a3 = *(const uint32_t*)(pa + 8 * A_ROWB + 16);
                #pragma unroll
                for (int j = 0; j < 8; j++)
                    mma_tf32(acc[i][j], a0, a1, a2, a3, b0[j], b1[j]);
            }
        }

        if (c < 63){
            char* stAn = dsm + (s ^ 1) * STAGE_A;
            char* stBn = dsm + B_OFF + (s ^ 1) * STAGE_B;
            STAGE_STORE(stAn, stBn);
            __syncthreads();
        }
    }

    // ---- epilogue: acc + bias -> y ----
    float bias0[8], bias1[8];
    #pragma unroll
    for (int j = 0; j < 8; j++){
        const int gn = n0 + wn + j * 8 + la3 * 2;
        bias0[j] = __ldg(bc + gn);
        bias1[j] = __ldg(bc + gn + 1);
    }
    #pragma unroll
    for (int i = 0; i < 4; i++){
        const int gm = m0 + wm + i * 16 + lg;
        #pragma unroll
        for (int j = 0; j < 8; j++){
            const int gn = n0 + wn + j * 8 + la3 * 2;
            float2 v0 = make_float2(acc[i][j][0] + bias0[j], acc[i][j][1] + bias1[j]);
            float2 v1 = make_float2(acc[i][j][2] + bias0[j], acc[i][j][3] + bias1[j]);
            *(float2*)(yb + (size_t)gm * ODIM + gn)       = v0;
            *(float2*)(yb + (size_t)(gm + 8) * ODIM + gn) = v1;
        }
    }
}

extern "C" void kernel_launch(void* const* d_in, const int* in_sizes, int n_in,
                              void* d_out, int out_size)
{
    const float* x       = (const float*)d_in[0];
    const int*   cat_ids = (const int*)  d_in[1];
    const float* W       = (const float*)d_in[2];
    const float* bias    = (const float*)d_in[3];
    float*       y       = (float*)d_out;

    cudaFuncSetAttribute(cslin_mma4_kernel,
                         cudaFuncAttributeMaxDynamicSharedMemorySize, SMEM_DYN);
    dim3 grid(1024 / 128, 512 / 128, 64);   // (8, 4, 64)
    cslin_mma4_kernel<<<grid, 128, SMEM_DYN>>>(x, cat_ids, W, bias, y);
}

// round 7
// speedup vs baseline: 1.2225x; 1.2225x over previous
#include <cuda_runtime.h>
#include <cstdint>

// CategorySpecificLinear via mma.sync.m16n8k8 TF32 (base sm_103; tcgen05 is
// rejected by this bench's ptxas target).
//
// Round 7: CTA tile 256(M) x 128(N), BK=64 (16 chunks -> half the barriers of
// r4), 8 warps (4Mx2N), warp tile 64x64. Two-batch staging interleaved with
// the 8 k-steps. A stored as 2 sub-tiles of pitch-36-f32 rows (conflict-free,
// no XOR math); B rows pitch 136 f32. Double-buffered, cvt.rna fp32->tf32.

#define A_SUB    36864                    // 256 rows x 144 B
#define STAGE_A  (2 * A_SUB)              // 73728
#define B_ROWB   544                      // 136 f32 per B row
#define STAGE_B  (64 * B_ROWB)            // 34816
#define B_OFF    (2 * STAGE_A)            // 147456
#define SMEM_DYN (2 * STAGE_A + 2 * STAGE_B)   // 217088

static __device__ __forceinline__ uint32_t f2tf(float f){
    uint32_t r; asm("cvt.rna.tf32.f32 %0, %1;" : "=r"(r) : "f"(f)); return r;
}

static __device__ __forceinline__ void mma_tf32(float d[4],
                                                uint32_t a0, uint32_t a1,
                                                uint32_t a2, uint32_t a3,
                                                uint32_t b0, uint32_t b1){
    asm volatile(
        "mma.sync.aligned.m16n8k8.row.col.f32.tf32.tf32.f32 "
        "{%0,%1,%2,%3}, {%4,%5,%6,%7}, {%8,%9}, {%0,%1,%2,%3};"
        : "+f"(d[0]), "+f"(d[1]), "+f"(d[2]), "+f"(d[3])
        : "r"(a0), "r"(a1), "r"(a2), "r"(a3), "r"(b0), "r"(b1));
}

__global__ __launch_bounds__(256, 1)
void cslin_mma5_kernel(const float* __restrict__ x,
                       const int*   __restrict__ cat_ids,
                       const float* __restrict__ W,
                       const float* __restrict__ bias,
                       float*       __restrict__ y)
{
    constexpr int IDIM = 1024, ODIM = 1024, TDIM = 512;
    extern __shared__ char dsm[];

    const int tid  = threadIdx.x;
    const int wid  = tid >> 5;
    const int lane = tid & 31;
    const int la3  = lane & 3;
    const int lg   = lane >> 2;

    const int n0 = blockIdx.x * 128;
    const int m0 = blockIdx.y * 256;
    const int bb = blockIdx.z;
    const int cat = __ldg(cat_ids + bb);

    const float* xb = x + (size_t)bb  * TDIM * IDIM;
    const float* Wc = W + (size_t)cat * IDIM * ODIM;
    const float* bc = bias + (size_t)cat * ODIM;
    float*       yb = y + (size_t)bb  * TDIM * ODIM;

    // ---- loader geometry ----
    // A: thread t covers rows (t>>2)+64i (i<4), k-bytes (t&3)*32 .. +31 of a
    //    32-k sub-tile; 8 float4 per sub-tile.
    const float* aG = xb + (size_t)(m0 + (tid >> 2)) * IDIM + ((tid & 3) << 3);
    const uint32_t aS = (uint32_t)((tid >> 2) * 144 + (tid & 3) * 32); // +i*9216,+h*16
    // B: thread t covers k-rows (t>>3)+32hb, col pieces (t&7)*16B + i*128B.
    const float* bG = Wc + (size_t)(tid >> 3) * ODIM + n0 + ((tid & 7) << 2);
    const uint32_t bS = (uint32_t)((tid >> 3) * B_ROWB + ((tid & 7) << 4)); // +hb*17408,+i*128

    // ---- warp tile 64x64 ----
    const int wm = (wid & 3) * 64;
    const int wn = (wid >> 2) * 64;

    uint32_t rA[4];
    #pragma unroll
    for (int i = 0; i < 4; i++) rA[i] = (uint32_t)((wm + i * 16 + lg) * 144);
    uint32_t bN[8];
    #pragma unroll
    for (int j = 0; j < 8; j++) bN[j] = (uint32_t)((wn + j * 8 + lg) * 4);
    const uint32_t aKf   = (uint32_t)(la3 * 4);
    const uint32_t bKrow = (uint32_t)(la3 * B_ROWB);

    float acc[4][8][4];
    #pragma unroll
    for (int i = 0; i < 4; i++)
        #pragma unroll
        for (int j = 0; j < 8; j++)
            #pragma unroll
            for (int q = 0; q < 4; q++) acc[i][j][q] = 0.f;

    float4 av[8], bv[4];

    // ---- staging macros ----
#define LDG_A(SUB, KC)                                                        \
    do { _Pragma("unroll")                                                    \
        for (int i = 0; i < 4; i++)                                           \
            _Pragma("unroll")                                                 \
            for (int h = 0; h < 2; h++)                                       \
                av[i*2+h] = *(const float4*)(aG + (size_t)(64*i)*IDIM         \
                                             + (KC) + (SUB)*32 + 4*h);        \
    } while (0)
#define STS_A(SUB, STA)                                                       \
    do { _Pragma("unroll")                                                    \
        for (int i = 0; i < 4; i++)                                           \
            _Pragma("unroll")                                                 \
            for (int h = 0; h < 2; h++)                                       \
                *(uint4*)((STA) + (SUB)*A_SUB + aS + (uint32_t)(i*9216+h*16)) = \
                    make_uint4(f2tf(av[i*2+h].x), f2tf(av[i*2+h].y),          \
                               f2tf(av[i*2+h].z), f2tf(av[i*2+h].w));         \
    } while (0)
#define LDG_B(HB, KC)                                                         \
    do { _Pragma("unroll")                                                    \
        for (int i = 0; i < 4; i++)                                           \
            bv[i] = *(const float4*)(bG + (size_t)((KC) + (HB)*32)*ODIM + 32*i); \
    } while (0)
#define STS_B(HB, STB)                                                        \
    do { _Pragma("unroll")                                                    \
        for (int i = 0; i < 4; i++)                                           \
            *(uint4*)((STB) + bS + (uint32_t)((HB)*17408 + i*128)) =          \
                make_uint4(f2tf(bv[i].x), f2tf(bv[i].y),                      \
                           f2tf(bv[i].z), f2tf(bv[i].w));                     \
    } while (0)

#define KSTEP(KS, STA, STB)                                                   \
    do { uint32_t b0[8], b1[8];                                               \
        const char* pb = (STB) + bKrow + (KS)*4352;                           \
        _Pragma("unroll")                                                     \
        for (int j = 0; j < 8; j++){                                          \
            b0[j] = *(const uint32_t*)(pb + bN[j]);                           \
            b1[j] = *(const uint32_t*)(pb + bN[j] + 4*B_ROWB);                \
        }                                                                     \
        _Pragma("unroll")                                                     \
        for (int i = 0; i < 4; i++){                                          \
            const char* pa = (STA) + ((KS)>>2)*A_SUB + ((KS)&3)*32 + aKf + rA[i]; \
            const uint32_t a0 = *(const uint32_t*)(pa);                       \
            const uint32_t a1 = *(const uint32_t*)(pa + 8*144);               \
            const uint32_t a2 = *(const uint32_t*)(pa + 16);                  \
            const uint32_t a3 = *(const uint32_t*)(pa + 8*144 + 16);          \
            _Pragma("unroll")                                                 \
            for (int j = 0; j < 8; j++)                                       \
                mma_tf32(acc[i][j], a0, a1, a2, a3, b0[j], b1[j]);            \
        }                                                                     \
    } while (0)

    // ---- prologue: stage chunk 0 into stage 0 ----
    LDG_A(0, 0); STS_A(0, dsm);
    LDG_B(0, 0); STS_B(0, dsm + B_OFF);
    LDG_A(1, 0); STS_A(1, dsm);
    LDG_B(1, 0); STS_B(1, dsm + B_OFF);
    __syncthreads();

    // ---- main loop: 16 chunks of BK=64 ----
    for (int c = 0; c < 16; c++){
        const int s = c & 1;
        const char* stA = dsm + s * STAGE_A;
        const char* stB = dsm + B_OFF + s * STAGE_B;
        char* stAn = dsm + (s ^ 1) * STAGE_A;
        char* stBn = dsm + B_OFF + (s ^ 1) * STAGE_B;
        const int kc = (c + 1) * 64;

        if (c < 15){ LDG_A(0, kc); LDG_B(0, kc); }

        KSTEP(0, stA, stB);
        KSTEP(1, stA, stB);

        if (c < 15){
            STS_A(0, stAn); STS_B(0, stBn);
            LDG_A(1, kc);   LDG_B(1, kc);
        }

        KSTEP(2, stA, stB);
        KSTEP(3, stA, stB);
        KSTEP(4, stA, stB);
        KSTEP(5, stA, stB);

        if (c < 15){ STS_A(1, stAn); STS_B(1, stBn); }

        KSTEP(6, stA, stB);
        KSTEP(7, stA, stB);

        if (c < 15) __syncthreads();
    }

    // ---- epilogue: acc + bias -> y ----
    float bias0[8], bias1[8];
    #pragma unroll
    for (int j = 0; j < 8; j++){
        const int gn = n0 + wn + j * 8 + la3 * 2;
        bias0[j] = __ldg(bc + gn);
        bias1[j] = __ldg(bc + gn + 1);
    }
    #pragma unroll
    for (int i = 0; i < 4; i++){
        const int gm = m0 + wm + i * 16 + lg;
        #pragma unroll
        for (int j = 0; j < 8; j++){
            const int gn = n0 + wn + j * 8 + la3 * 2;
            float2 v0 = make_float2(acc[i][j][0] + bias0[j], acc[i][j][1] + bias1[j]);
            float2 v1 = make_float2(acc[i][j][2] + bias0[j], acc[i][j][3] + bias1[j]);
            *(float2*)(yb + (size_t)gm * ODIM + gn)       = v0;
            *(float2*)(yb + (size_t)(gm + 8) * ODIM + gn) = v1;
        }
    }
}

extern "C" void kernel_launch(void* const* d_in, const int* in_sizes, int n_in,
                              void* d_out, int out_size)
{
    const float* x       = (const float*)d_in[0];
    const int*   cat_ids = (const int*)  d_in[1];
    const float* W       = (const float*)d_in[2];
    const float* bias    = (const float*)d_in[3];
    float*       y       = (float*)d_out;

    cudaFuncSetAttribute(cslin_mma5_kernel,
                         cudaFuncAttributeMaxDynamicSharedMemorySize, SMEM_DYN);
    dim3 grid(1024 / 128, 512 / 256, 64);   // (8, 2, 64)
    cslin_mma5_kernel<<<grid, 256, SMEM_DYN>>>(x, cat_ids, W, bias, y);
}

// round 8
// speedup vs baseline: 1.5812x; 1.2934x over previous
#include <cuda_runtime.h>
#include <cstdint>

// CategorySpecificLinear via mma.sync.m16n8k8 TF32 (base sm_103; tcgen05 is
// rejected by this bench's ptxas target).
//
// Round 8: r4 geometry (CTA 256Mx128N, BK=32, 8 warps 4Mx2N, warp tile 64x64)
// with cp.async (LDGSTS) 4-stage staging -> no staging registers, and tf32
// rounding applied on fragments after LDS. Fragment double-buffering across
// k-steps hides LDS latency. A: 128B rows + XOR swizzle (conflict-free),
// B: pitch-136-f32 rows (conflict-free).

#define A_STAGE  32768                 // 256 x 32 f32, 128B rows
#define B_STAGE  17408                 // 32 x 136 f32
#define B_REG    (4 * A_STAGE)         // 131072
#define SMEM_DYN (4 * A_STAGE + 4 * B_STAGE)   // 200704

static __device__ __forceinline__ uint32_t smem_u32(const void* p){
    uint32_t a;
    asm("{ .reg .u64 t; cvta.to.shared.u64 t, %1; cvt.u32.u64 %0, t; }" : "=r"(a) : "l"(p));
    return a;
}
static __device__ __forceinline__ void cp16(uint32_t dst, const void* src){
    asm volatile("cp.async.cg.shared.global [%0], [%1], 16;"
                 :: "r"(dst), "l"(src) : "memory");
}
static __device__ __forceinline__ uint32_t f2tf(uint32_t bits){
    uint32_t r;
    asm("cvt.rna.tf32.f32 %0, %1;" : "=r"(r) : "f"(__uint_as_float(bits)));
    return r;
}
static __device__ __forceinline__ void mma_tf32(float d[4],
                                                uint32_t a0, uint32_t a1,
                                                uint32_t a2, uint32_t a3,
                                                uint32_t b0, uint32_t b1){
    asm volatile(
        "mma.sync.aligned.m16n8k8.row.col.f32.tf32.tf32.f32 "
        "{%0,%1,%2,%3}, {%4,%5,%6,%7}, {%8,%9}, {%0,%1,%2,%3};"
        : "+f"(d[0]), "+f"(d[1]), "+f"(d[2]), "+f"(d[3])
        : "r"(a0), "r"(a1), "r"(a2), "r"(a3), "r"(b0), "r"(b1));
}

__global__ __launch_bounds__(256, 1)
void cslin_mma6_kernel(const float* __restrict__ x,
                       const int*   __restrict__ cat_ids,
                       const float* __restrict__ W,
                       const float* __restrict__ bias,
                       float*       __restrict__ y)
{
    constexpr int IDIM = 1024, ODIM = 1024, TDIM = 512;
    extern __shared__ char dsm[];

    const int tid  = threadIdx.x;
    const int wid  = tid >> 5;
    const int lane = tid & 31;
    const int la3  = lane & 3;
    const int lg   = lane >> 2;

    const int n0 = blockIdx.x * 128;
    const int m0 = blockIdx.y * 256;
    const int bb = blockIdx.z;
    const int cat = __ldg(cat_ids + bb);

    const float* xb = x + (size_t)bb  * TDIM * IDIM;
    const float* Wc = W + (size_t)cat * IDIM * ODIM;
    const float* bc = bias + (size_t)cat * ODIM;
    float*       yb = y + (size_t)bb  * TDIM * ODIM;

    // ---- cp.async geometry ----
    // A: 2048 granules(16B)/chunk; thread t: rows (t>>3)+32i (i<8), gcol t&7.
    const float* aSrc = xb + (size_t)(m0 + (tid >> 3)) * IDIM + ((tid & 7) << 2);
    const uint32_t aDst = smem_u32(dsm)
        + (uint32_t)((tid >> 3) * 128)
        + (uint32_t)((((tid & 7) << 4)) ^ ((((tid >> 3) & 7)) << 4));   // +i*4096,+s*A_STAGE
    // B: 1024 granules/chunk; thread t: rows (t>>5)+8i (i<4), gcol t&31.
    const float* bSrc = Wc + (size_t)(tid >> 5) * ODIM + n0 + ((tid & 31) << 2);
    const uint32_t bDst = smem_u32(dsm) + B_REG
        + (uint32_t)((tid >> 5) * 544 + ((tid & 31) << 4));             // +i*4352,+s*B_STAGE

#define ISSUE(KC, S)                                                          \
    do {                                                                      \
        const float* _as = aSrc + (KC);                                       \
        const uint32_t _ad = aDst + (uint32_t)((S) * A_STAGE);                \
        _Pragma("unroll")                                                     \
        for (int i = 0; i < 8; i++)                                           \
            cp16(_ad + (uint32_t)(i * 4096), _as + (size_t)(32 * i) * IDIM);  \
        const float* _bs = bSrc + (size_t)(KC) * ODIM;                        \
        const uint32_t _bd = bDst + (uint32_t)((S) * B_STAGE);                \
        _Pragma("unroll")                                                     \
        for (int i = 0; i < 4; i++)                                           \
            cp16(_bd + (uint32_t)(i * 4352), _bs + (size_t)(8 * i) * ODIM);   \
    } while (0)

    // ---- warp tile 64x64 ----
    const int wm = (wid & 3) * 64;
    const int wn = (wid >> 2) * 64;

    const uint32_t swzA = (uint32_t)(lg << 4);
    uint32_t rA[4];
    #pragma unroll
    for (int i = 0; i < 4; i++) rA[i] = (uint32_t)((wm + i * 16 + lg) * 128);
    uint32_t bN[8];
    #pragma unroll
    for (int j = 0; j < 8; j++) bN[j] = (uint32_t)((wn + j * 8 + lg) * 4);
    const uint32_t bKrow = (uint32_t)(la3 * 544);

    float acc[4][8][4];
    #pragma unroll
    for (int i = 0; i < 4; i++)
        #pragma unroll
        for (int j = 0; j < 8; j++)
            #pragma unroll
            for (int q = 0; q < 4; q++) acc[i][j][q] = 0.f;

    uint32_t fa0[16], fb0[16], fa1[16], fb1[16];

#define LOAD_FRAGS(FA, FB, SA, SB, KS)                                        \
    do {                                                                      \
        const char* _pb = (SB) + bKrow + (KS) * 4352;                         \
        _Pragma("unroll")                                                     \
        for (int j = 0; j < 8; j++){                                          \
            FB[2*j]   = f2tf(*(const uint32_t*)(_pb + bN[j]));                \
            FB[2*j+1] = f2tf(*(const uint32_t*)(_pb + bN[j] + 2176));         \
        }                                                                     \
        const uint32_t _c0 = ((uint32_t)((KS) * 32 + la3 * 4)) ^ swzA;        \
        const uint32_t _c1 = _c0 ^ 16u;                                       \
        _Pragma("unroll")                                                     \
        for (int i = 0; i < 4; i++){                                          \
            const char* _pa = (SA) + rA[i];                                   \
            FA[4*i]   = f2tf(*(const uint32_t*)(_pa + _c0));                  \
            FA[4*i+1] = f2tf(*(const uint32_t*)(_pa + 1024 + _c0));           \
            FA[4*i+2] = f2tf(*(const uint32_t*)(_pa + _c1));                  \
            FA[4*i+3] = f2tf(*(const uint32_t*)(_pa + 1024 + _c1));           \
        }                                                                     \
    } while (0)

#define MMA_BLOCK(FA, FB)                                                     \
    do {                                                                      \
        _Pragma("unroll")                                                     \
        for (int i = 0; i < 4; i++)                                           \
            _Pragma("unroll")                                                 \
            for (int j = 0; j < 8; j++)                                       \
                mma_tf32(acc[i][j], FA[4*i], FA[4*i+1], FA[4*i+2], FA[4*i+3], \
                         FB[2*j], FB[2*j+1]);                                 \
    } while (0)

    // ---- prologue: issue chunks 0..2 ----
    ISSUE(0, 0);
    asm volatile("cp.async.commit_group;" ::: "memory");
    ISSUE(32, 1);
    asm volatile("cp.async.commit_group;" ::: "memory");
    ISSUE(64, 2);
    asm volatile("cp.async.commit_group;" ::: "memory");

    // ---- main loop: 32 chunks of BK=32 ----
    for (int c = 0; c < 32; c++){
        asm volatile("cp.async.wait_group 2;" ::: "memory");
        __syncthreads();

        if (c + 3 < 32) ISSUE((c + 3) * 32, (c + 3) & 3);
        asm volatile("cp.async.commit_group;" ::: "memory");

        const char* sA = dsm + (c & 3) * A_STAGE;
        const char* sB = dsm + B_REG + (c & 3) * B_STAGE;

        LOAD_FRAGS(fa0, fb0, sA, sB, 0);
        LOAD_FRAGS(fa1, fb1, sA, sB, 1);
        MMA_BLOCK(fa0, fb0);
        LOAD_FRAGS(fa0, fb0, sA, sB, 2);
        MMA_BLOCK(fa1, fb1);
        LOAD_FRAGS(fa1, fb1, sA, sB, 3);
        MMA_BLOCK(fa0, fb0);
        MMA_BLOCK(fa1, fb1);
    }

    // ---- epilogue: acc + bias -> y ----
    float bias0[8], bias1[8];
    #pragma unroll
    for (int j = 0; j < 8; j++){
        const int gn = n0 + wn + j * 8 + la3 * 2;
        bias0[j] = __ldg(bc + gn);
        bias1[j] = __ldg(bc + gn + 1);
    }
    #pragma unroll
    for (int i = 0; i < 4; i++){
        const int gm = m0 + wm + i * 16 + lg;
        #pragma unroll
        for (int j = 0; j < 8; j++){
            const int gn = n0 + wn + j * 8 + la3 * 2;
            float2 v0 = make_float2(acc[i][j][0] + bias0[j], acc[i][j][1] + bias1[j]);
            float2 v1 = make_float2(acc[i][j][2] + bias0[j], acc[i][j][3] + bias1[j]);
            *(float2*)(yb + (size_t)gm * ODIM + gn)       = v0;
            *(float2*)(yb + (size_t)(gm + 8) * ODIM + gn) = v1;
        }
    }
}

extern "C" void kernel_launch(void* const* d_in, const int* in_sizes, int n_in,
                              void* d_out, int out_size)
{
    const float* x       = (const float*)d_in[0];
    const int*   cat_ids = (const int*)  d_in[1];
    const float* W       = (const float*)d_in[2];
    const float* bias    = (const float*)d_in[3];
    float*       y       = (float*)d_out;

    cudaFuncSetAttribute(cslin_mma6_kernel,
                         cudaFuncAttributeMaxDynamicSharedMemorySize, SMEM_DYN);
    dim3 grid(1024 / 128, 512 / 256, 64);   // (8, 2, 64)
    cslin_mma6_kernel<<<grid, 256, SMEM_DYN>>>(x, cat_ids, W, bias, y);
}

// round 9
// speedup vs baseline: 1.7190x; 1.0871x over previous
#include <cuda_runtime.h>
#include <cstdint>

// CategorySpecificLinear via mma.sync.m16n8k8 TF32 (base sm_103; tcgen05 is
// rejected by this bench's ptxas target).
//
// Round 9: r8 (CTA 256Mx128N, BK=32, 8 warps 4Mx2N, warp 64x64, 4-stage
// cp.async) + cross-chunk fragment preload: the barrier/ISSUE moves mid-chunk
// and next chunk's ks0 fragments load before the boundary, so MMAs restart
// immediately after the barrier. Loop unrolled x4 for constant stage offsets.

#define A_STAGE  32768                 // 256 x 32 f32, 128B rows
#define B_STAGE  17408                 // 32 x 136 f32
#define B_REG    (4 * A_STAGE)         // 131072
#define SMEM_DYN (4 * A_STAGE + 4 * B_STAGE)   // 200704

static __device__ __forceinline__ uint32_t smem_u32(const void* p){
    uint32_t a;
    asm("{ .reg .u64 t; cvta.to.shared.u64 t, %1; cvt.u32.u64 %0, t; }" : "=r"(a) : "l"(p));
    return a;
}
static __device__ __forceinline__ void cp16(uint32_t dst, const void* src){
    asm volatile("cp.async.cg.shared.global [%0], [%1], 16;"
                 :: "r"(dst), "l"(src) : "memory");
}
static __device__ __forceinline__ uint32_t f2tf(uint32_t bits){
    uint32_t r;
    asm("cvt.rna.tf32.f32 %0, %1;" : "=r"(r) : "f"(__uint_as_float(bits)));
    return r;
}
static __device__ __forceinline__ void mma_tf32(float d[4],
                                                uint32_t a0, uint32_t a1,
                                                uint32_t a2, uint32_t a3,
                                                uint32_t b0, uint32_t b1){
    asm volatile(
        "mma.sync.aligned.m16n8k8.row.col.f32.tf32.tf32.f32 "
        "{%0,%1,%2,%3}, {%4,%5,%6,%7}, {%8,%9}, {%0,%1,%2,%3};"
        : "+f"(d[0]), "+f"(d[1]), "+f"(d[2]), "+f"(d[3])
        : "r"(a0), "r"(a1), "r"(a2), "r"(a3), "r"(b0), "r"(b1));
}

__global__ __launch_bounds__(256, 1)
void cslin_mma7_kernel(const float* __restrict__ x,
                       const int*   __restrict__ cat_ids,
                       const float* __restrict__ W,
                       const float* __restrict__ bias,
                       float*       __restrict__ y)
{
    constexpr int IDIM = 1024, ODIM = 1024, TDIM = 512;
    extern __shared__ char dsm[];

    const int tid  = threadIdx.x;
    const int wid  = tid >> 5;
    const int lane = tid & 31;
    const int la3  = lane & 3;
    const int lg   = lane >> 2;

    const int n0 = blockIdx.x * 128;
    const int m0 = blockIdx.y * 256;
    const int bb = blockIdx.z;
    const int cat = __ldg(cat_ids + bb);

    const float* xb = x + (size_t)bb  * TDIM * IDIM;
    const float* Wc = W + (size_t)cat * IDIM * ODIM;
    const float* bc = bias + (size_t)cat * ODIM;
    float*       yb = y + (size_t)bb  * TDIM * ODIM;

    // ---- cp.async geometry ----
    const float* aSrc = xb + (size_t)(m0 + (tid >> 3)) * IDIM + ((tid & 7) << 2);
    const uint32_t aDst = smem_u32(dsm)
        + (uint32_t)((tid >> 3) * 128)
        + (uint32_t)((((tid & 7) << 4)) ^ ((((tid >> 3) & 7)) << 4));
    const float* bSrc = Wc + (size_t)(tid >> 5) * ODIM + n0 + ((tid & 31) << 2);
    const uint32_t bDst = smem_u32(dsm) + B_REG
        + (uint32_t)((tid >> 5) * 544 + ((tid & 31) << 4));

#define ISSUE(KC, S)                                                          \
    do {                                                                      \
        const float* _as = aSrc + (KC);                                       \
        const uint32_t _ad = aDst + (uint32_t)((S) * A_STAGE);                \
        _Pragma("unroll")                                                     \
        for (int i = 0; i < 8; i++)                                           \
            cp16(_ad + (uint32_t)(i * 4096), _as + (size_t)(32 * i) * IDIM);  \
        const float* _bs = bSrc + (size_t)(KC) * ODIM;                        \
        const uint32_t _bd = bDst + (uint32_t)((S) * B_STAGE);                \
        _Pragma("unroll")                                                     \
        for (int i = 0; i < 4; i++)                                           \
            cp16(_bd + (uint32_t)(i * 4352), _bs + (size_t)(8 * i) * ODIM);   \
    } while (0)

    // ---- warp tile 64x64 ----
    const int wm = (wid & 3) * 64;
    const int wn = (wid >> 2) * 64;

    const uint32_t swzA = (uint32_t)(lg << 4);
    uint32_t rA[4];
    #pragma unroll
    for (int i = 0; i < 4; i++) rA[i] = (uint32_t)((wm + i * 16 + lg) * 128);
    uint32_t bN[8];
    #pragma unroll
    for (int j = 0; j < 8; j++) bN[j] = (uint32_t)((wn + j * 8 + lg) * 4);
    const uint32_t bKrow = (uint32_t)(la3 * 544);

    float acc[4][8][4];
    #pragma unroll
    for (int i = 0; i < 4; i++)
        #pragma unroll
        for (int j = 0; j < 8; j++)
            #pragma unroll
            for (int q = 0; q < 4; q++) acc[i][j][q] = 0.f;

    uint32_t fa0[16], fb0[16], fa1[16], fb1[16];

#define LOAD_FRAGS(FA, FB, SA, SB, KS)                                        \
    do {                                                                      \
        const char* _pb = (SB) + bKrow + (KS) * 4352;                         \
        _Pragma("unroll")                                                     \
        for (int j = 0; j < 8; j++){                                          \
            FB[2*j]   = f2tf(*(const uint32_t*)(_pb + bN[j]));                \
            FB[2*j+1] = f2tf(*(const uint32_t*)(_pb + bN[j] + 2176));         \
        }                                                                     \
        const uint32_t _c0 = ((uint32_t)((KS) * 32 + la3 * 4)) ^ swzA;        \
        const uint32_t _c1 = _c0 ^ 16u;                                       \
        _Pragma("unroll")                                                     \
        for (int i = 0; i < 4; i++){                                          \
            const char* _pa = (SA) + rA[i];                                   \
            FA[4*i]   = f2tf(*(const uint32_t*)(_pa + _c0));                  \
            FA[4*i+1] = f2tf(*(const uint32_t*)(_pa + 1024 + _c0));           \
            FA[4*i+2] = f2tf(*(const uint32_t*)(_pa + _c1));                  \
            FA[4*i+3] = f2tf(*(const uint32_t*)(_pa + 1024 + _c1));           \
        }                                                                     \
    } while (0)

#define MMA_BLOCK(FA, FB)                                                     \
    do {                                                                      \
        _Pragma("unroll")                                                     \
        for (int i = 0; i < 4; i++)                                           \
            _Pragma("unroll")                                                 \
            for (int j = 0; j < 8; j++)                                       \
                mma_tf32(acc[i][j], FA[4*i], FA[4*i+1], FA[4*i+2], FA[4*i+3], \
                         FB[2*j], FB[2*j+1]);                                 \
    } while (0)

    // One chunk, stage index S is a compile-time constant.
    // Mid-chunk: wait(stage c+1 resident) + barrier + ISSUE(c+3); after last
    // MMA, preload chunk c+1's ks0 fragments (stage untouched until c+2).
#define CHUNK_BODY(C, S)                                                      \
    do {                                                                      \
        const char* sA = dsm + (S) * A_STAGE;                                 \
        const char* sB = dsm + B_REG + (S) * B_STAGE;                         \
        LOAD_FRAGS(fa1, fb1, sA, sB, 1);                                      \
        MMA_BLOCK(fa0, fb0);                                                  \
        LOAD_FRAGS(fa0, fb0, sA, sB, 2);                                      \
        MMA_BLOCK(fa1, fb1);                                                  \
        LOAD_FRAGS(fa1, fb1, sA, sB, 3);                                      \
        MMA_BLOCK(fa0, fb0);                                                  \
        if ((C) + 3 < 32){                                                    \
            asm volatile("cp.async.wait_group 1;" ::: "memory");              \
            __syncthreads();                                                  \
            ISSUE(((C) + 3) * 32, ((S) + 3) & 3);                             \
            asm volatile("cp.async.commit_group;" ::: "memory");              \
        } else {                                                              \
            asm volatile("cp.async.wait_group 0;" ::: "memory");              \
            __syncthreads();                                                  \
        }                                                                     \
        MMA_BLOCK(fa1, fb1);                                                  \
        if ((C) + 1 < 32){                                                    \
            const char* nA = dsm + (((S) + 1) & 3) * A_STAGE;                 \
            const char* nB = dsm + B_REG + (((S) + 1) & 3) * B_STAGE;         \
            LOAD_FRAGS(fa0, fb0, nA, nB, 0);                                  \
        }                                                                     \
    } while (0)

    // ---- prologue: issue chunks 0..2, preload chunk 0 ks0 ----
    ISSUE(0, 0);
    asm volatile("cp.async.commit_group;" ::: "memory");
    ISSUE(32, 1);
    asm volatile("cp.async.commit_group;" ::: "memory");
    ISSUE(64, 2);
    asm volatile("cp.async.commit_group;" ::: "memory");
    asm volatile("cp.async.wait_group 1;" ::: "memory");   // stages 0,1 ready
    __syncthreads();
    LOAD_FRAGS(fa0, fb0, dsm, dsm + B_REG, 0);

    // ---- main loop: 32 chunks, unrolled x4 (constant stage offsets) ----
    for (int cb = 0; cb < 32; cb += 4){
        CHUNK_BODY(cb + 0, 0);
        CHUNK_BODY(cb + 1, 1);
        CHUNK_BODY(cb + 2, 2);
        CHUNK_BODY(cb + 3, 3);
    }

    // ---- epilogue: acc + bias -> y ----
    float bias0[8], bias1[8];
    #pragma unroll
    for (int j = 0; j < 8; j++){
        const int gn = n0 + wn + j * 8 + la3 * 2;
        bias0[j] = __ldg(bc + gn);
        bias1[j] = __ldg(bc + gn + 1);
    }
    #pragma unroll
    for (int i = 0; i < 4; i++){
        const int gm = m0 + wm + i * 16 + lg;
        #pragma unroll
        for (int j = 0; j < 8; j++){
            const int gn = n0 + wn + j * 8 + la3 * 2;
            float2 v0 = make_float2(acc[i][j][0] + bias0[j], acc[i][j][1] + bias1[j]);
            float2 v1 = make_float2(acc[i][j][2] + bias0[j], acc[i][j][3] + bias1[j]);
            *(float2*)(yb + (size_t)gm * ODIM + gn)       = v0;
            *(float2*)(yb + (size_t)(gm + 8) * ODIM + gn) = v1;
        }
    }
}

extern "C" void kernel_launch(void* const* d_in, const int* in_sizes, int n_in,
                              void* d_out, int out_size)
{
    const float* x       = (const float*)d_in[0];
    const int*   cat_ids = (const int*)  d_in[1];
    const float* W       = (const float*)d_in[2];
    const float* bias    = (const float*)d_in[3];
    float*       y       = (float*)d_out;

    cudaFuncSetAttribute(cslin_mma7_kernel,
                         cudaFuncAttributeMaxDynamicSharedMemorySize, SMEM_DYN);
    dim3 grid(1024 / 128, 512 / 256, 64);   // (8, 2, 64)
    cslin_mma7_kernel<<<grid, 256, SMEM_DYN>>>(x, cat_ids, W, bias, y);
}

// round 10
// speedup vs baseline: 1.7208x; 1.0010x over previous
#include <cuda_runtime.h>
#include <cstdint>

// CategorySpecificLinear via mma.sync.m16n8k8 TF32 (base sm_103; tcgen05 is
// rejected by this bench's ptxas target).
//
// Round 10: r9 schedule (CTA 256Mx128N, BK=32, 8 warps 4Mx2N, warp 64x64,
// 4-stage cp.async, mid-chunk barrier, cross-chunk frag preload) with a
// register/ALU diet: fragment addresses are base + immediate offsets instead
// of precomputed arrays (rA[4]/bN[8] eliminated), cutting ~12 live regs and
// the IADD chains that pushed r9 to 255 regs (spills) and alu=25%.

#define A_STAGE  32768                 // 256 x 32 f32, 128B rows
#define B_STAGE  17408                 // 32 x 136 f32
#define B_REG    (4 * A_STAGE)         // 131072
#define SMEM_DYN (4 * A_STAGE + 4 * B_STAGE)   // 200704

static __device__ __forceinline__ uint32_t smem_u32(const void* p){
    uint32_t a;
    asm("{ .reg .u64 t; cvta.to.shared.u64 t, %1; cvt.u32.u64 %0, t; }" : "=r"(a) : "l"(p));
    return a;
}
static __device__ __forceinline__ void cp16(uint32_t dst, const void* src){
    asm volatile("cp.async.cg.shared.global [%0], [%1], 16;"
                 :: "r"(dst), "l"(src) : "memory");
}
static __device__ __forceinline__ uint32_t f2tf(uint32_t bits){
    uint32_t r;
    asm("cvt.rna.tf32.f32 %0, %1;" : "=r"(r) : "f"(__uint_as_float(bits)));
    return r;
}
static __device__ __forceinline__ void mma_tf32(float d[4],
                                                uint32_t a0, uint32_t a1,
                                                uint32_t a2, uint32_t a3,
                                                uint32_t b0, uint32_t b1){
    asm volatile(
        "mma.sync.aligned.m16n8k8.row.col.f32.tf32.tf32.f32 "
        "{%0,%1,%2,%3}, {%4,%5,%6,%7}, {%8,%9}, {%0,%1,%2,%3};"
        : "+f"(d[0]), "+f"(d[1]), "+f"(d[2]), "+f"(d[3])
        : "r"(a0), "r"(a1), "r"(a2), "r"(a3), "r"(b0), "r"(b1));
}
static __device__ __forceinline__ uint32_t lds32(const char* p){
    return *(const uint32_t*)p;
}

__global__ __launch_bounds__(256, 1)
void cslin_mma8_kernel(const float* __restrict__ x,
                       const int*   __restrict__ cat_ids,
                       const float* __restrict__ W,
                       const float* __restrict__ bias,
                       float*       __restrict__ y)
{
    constexpr int IDIM = 1024, ODIM = 1024, TDIM = 512;
    extern __shared__ char dsm[];

    const int tid  = threadIdx.x;
    const int wid  = tid >> 5;
    const int lane = tid & 31;
    const int la3  = lane & 3;
    const int lg   = lane >> 2;

    const int n0 = blockIdx.x * 128;
    const int m0 = blockIdx.y * 256;
    const int bb = blockIdx.z;
    const int cat = __ldg(cat_ids + bb);

    const float* xb = x + (size_t)bb  * TDIM * IDIM;
    const float* Wc = W + (size_t)cat * IDIM * ODIM;
    const float* bc = bias + (size_t)cat * ODIM;
    float*       yb = y + (size_t)bb  * TDIM * ODIM;

    // ---- cp.async geometry ----
    const float* aSrc = xb + (size_t)(m0 + (tid >> 3)) * IDIM + ((tid & 7) << 2);
    const uint32_t aDst = smem_u32(dsm)
        + (uint32_t)((tid >> 3) * 128)
        + (uint32_t)((((tid & 7) << 4)) ^ ((((tid >> 3) & 7)) << 4));
    const float* bSrc = Wc + (size_t)(tid >> 5) * ODIM + n0 + ((tid & 31) << 2);
    const uint32_t bDst = smem_u32(dsm) + B_REG
        + (uint32_t)((tid >> 5) * 544 + ((tid & 31) << 4));

#define ISSUE(KC, S)                                                          \
    do {                                                                      \
        const float* _as = aSrc + (KC);                                       \
        const uint32_t _ad = aDst + (uint32_t)((S) * A_STAGE);                \
        _Pragma("unroll")                                                     \
        for (int i = 0; i < 8; i++)                                           \
            cp16(_ad + (uint32_t)(i * 4096), _as + (size_t)(32 * i) * IDIM);  \
        const float* _bs = bSrc + (size_t)(KC) * ODIM;                        \
        const uint32_t _bd = bDst + (uint32_t)((S) * B_STAGE);                \
        _Pragma("unroll")                                                     \
        for (int i = 0; i < 4; i++)                                           \
            cp16(_bd + (uint32_t)(i * 4352), _bs + (size_t)(8 * i) * ODIM);   \
    } while (0)

    // ---- warp tile 64x64, compacted invariants ----
    const int wm = (wid & 3) * 64;
    const int wn = (wid >> 2) * 64;

    const uint32_t swzA = (uint32_t)(lg << 4);
    const uint32_t aInv = (uint32_t)((wm + lg) * 128);          // + i*2048 (+1024)
    const uint32_t bInv = (uint32_t)(la3 * 544 + (wn + lg) * 4); // + j*32 (+2176)
    const uint32_t aK   = (uint32_t)(la3 * 4);

    float acc[4][8][4];
    #pragma unroll
    for (int i = 0; i < 4; i++)
        #pragma unroll
        for (int j = 0; j < 8; j++)
            #pragma unroll
            for (int q = 0; q < 4; q++) acc[i][j][q] = 0.f;

    uint32_t fa0[16], fb0[16], fa1[16], fb1[16];

    // Fragment loads: bases are single registers, all lane offsets immediate.
#define LOAD_FRAGS(FA, FB, SA, SB, KS)                                        \
    do {                                                                      \
        const char* _pb = (SB) + (bInv + (KS) * 4352);                        \
        _Pragma("unroll")                                                     \
        for (int j = 0; j < 8; j++){                                          \
            FB[2*j]   = f2tf(lds32(_pb + j * 32));                            \
            FB[2*j+1] = f2tf(lds32(_pb + j * 32 + 2176));                     \
        }                                                                     \
        const uint32_t _c0 = ((uint32_t)((KS) * 32) + aK) ^ swzA;             \
        const char* _pa0 = (SA) + (aInv + _c0);                               \
        const char* _pa1 = (SA) + (aInv + (_c0 ^ 16u));                       \
        _Pragma("unroll")                                                     \
        for (int i = 0; i < 4; i++){                                          \
            FA[4*i]   = f2tf(lds32(_pa0 + i * 2048));                         \
            FA[4*i+1] = f2tf(lds32(_pa0 + i * 2048 + 1024));                  \
            FA[4*i+2] = f2tf(lds32(_pa1 + i * 2048));                         \
            FA[4*i+3] = f2tf(lds32(_pa1 + i * 2048 + 1024));                  \
        }                                                                     \
    } while (0)

#define MMA_BLOCK(FA, FB)                                                     \
    do {                                                                      \
        _Pragma("unroll")                                                     \
        for (int i = 0; i < 4; i++)                                           \
            _Pragma("unroll")                                                 \
            for (int j = 0; j < 8; j++)                                       \
                mma_tf32(acc[i][j], FA[4*i], FA[4*i+1], FA[4*i+2], FA[4*i+3], \
                         FB[2*j], FB[2*j+1]);                                 \
    } while (0)

#define CHUNK_BODY(C, S)                                                      \
    do {                                                                      \
        const char* sA = dsm + (S) * A_STAGE;                                 \
        const char* sB = dsm + B_REG + (S) * B_STAGE;                         \
        LOAD_FRAGS(fa1, fb1, sA, sB, 1);                                      \
        MMA_BLOCK(fa0, fb0);                                                  \
        LOAD_FRAGS(fa0, fb0, sA, sB, 2);                                      \
        MMA_BLOCK(fa1, fb1);                                                  \
        LOAD_FRAGS(fa1, fb1, sA, sB, 3);                                      \
        MMA_BLOCK(fa0, fb0);                                                  \
        if ((C) + 3 < 32){                                                    \
            asm volatile("cp.async.wait_group 1;" ::: "memory");              \
            __syncthreads();                                                  \
            ISSUE(((C) + 3) * 32, ((S) + 3) & 3);                             \
            asm volatile("cp.async.commit_group;" ::: "memory");              \
        } else {                                                              \
            asm volatile("cp.async.wait_group 0;" ::: "memory");              \
            __syncthreads();                                                  \
        }                                                                     \
        MMA_BLOCK(fa1, fb1);                                                  \
        if ((C) + 1 < 32){                                                    \
            const char* nA = dsm + (((S) + 1) & 3) * A_STAGE;                 \
            const char* nB = dsm + B_REG + (((S) + 1) & 3) * B_STAGE;         \
            LOAD_FRAGS(fa0, fb0, nA, nB, 0);                                  \
        }                                                                     \
    } while (0)

    // ---- prologue ----
    ISSUE(0, 0);
    asm volatile("cp.async.commit_group;" ::: "memory");
    ISSUE(32, 1);
    asm volatile("cp.async.commit_group;" ::: "memory");
    ISSUE(64, 2);
    asm volatile("cp.async.commit_group;" ::: "memory");
    asm volatile("cp.async.wait_group 1;" ::: "memory");
    __syncthreads();
    LOAD_FRAGS(fa0, fb0, dsm, dsm + B_REG, 0);

    // ---- main loop: 32 chunks, unrolled x4 ----
    for (int cb = 0; cb < 32; cb += 4){
        CHUNK_BODY(cb + 0, 0);
        CHUNK_BODY(cb + 1, 1);
        CHUNK_BODY(cb + 2, 2);
        CHUNK_BODY(cb + 3, 3);
    }

    // ---- epilogue: acc + bias -> y ----
    float bias0[8], bias1[8];
    #pragma unroll
    for (int j = 0; j < 8; j++){
        const int gn = n0 + wn + j * 8 + la3 * 2;
        bias0[j] = __ldg(bc + gn);
        bias1[j] = __ldg(bc + gn + 1);
    }
    #pragma unroll
    for (int i = 0; i < 4; i++){
        const int gm = m0 + wm + i * 16 + lg;
        #pragma unroll
        for (int j = 0; j < 8; j++){
            const int gn = n0 + wn + j * 8 + la3 * 2;
            float2 v0 = make_float2(acc[i][j][0] + bias0[j], acc[i][j][1] + bias1[j]);
            float2 v1 = make_float2(acc[i][j][2] + bias0[j], acc[i][j][3] + bias1[j]);
            *(float2*)(yb + (size_t)gm * ODIM + gn)       = v0;
            *(float2*)(yb + (size_t)(gm + 8) * ODIM + gn) = v1;
        }
    }
}

extern "C" void kernel_launch(void* const* d_in, const int* in_sizes, int n_in,
                              void* d_out, int out_size)
{
    const float* x       = (const float*)d_in[0];
    const int*   cat_ids = (const int*)  d_in[1];
    const float* W       = (const float*)d_in[2];
    const float* bias    = (const float*)d_in[3];
    float*       y       = (float*)d_out;

    cudaFuncSetAttribute(cslin_mma8_kernel,
                         cudaFuncAttributeMaxDynamicSharedMemorySize, SMEM_DYN);
    dim3 grid(1024 / 128, 512 / 256, 64);   // (8, 2, 64)
    cslin_mma8_kernel<<<grid, 256, SMEM_DYN>>>(x, cat_ids, W, bias, y);
}